// round 8
// baseline (speedup 1.0000x reference)
#include <cuda_runtime.h>
#include <cuda_bf16.h>
#include <cstdint>

#define C_DIM 1000
#define C_VEC 250            // C_DIM / 4
#define VPT 8                // ceil(C_VEC / 32)
#define ROWS_PER_CTA 8
#define NTHREADS (ROWS_PER_CTA * 32)
#define B_DIM 16384

__device__ int          g_labels[B_DIM];
__device__ float        g_scratch = 0.0f;
__device__ unsigned int g_count   = 0;

// ================= K1: per-row argmax of target =================
__global__ __launch_bounds__(NTHREADS, 5)
void argmax_kernel(const float* __restrict__ target) {
    const int lane = threadIdx.x & 31;
    const int wid  = threadIdx.x >> 5;
    const int row  = blockIdx.x * ROWS_PER_CTA + wid;

    const float4* tg = reinterpret_cast<const float4*>(target + (size_t)row * C_DIM);
    const float NEG_INF = -3.402823466e+38f;

    // single batched load phase: 8 float4 per lane (MLP_p1 = 8)
    float4 t[VPT];
    #pragma unroll
    for (int k = 0; k < VPT; k++) {
        int v = lane + 32 * k;
        if (v < C_VEC) t[k] = tg[v];
        else           t[k] = make_float4(NEG_INF, NEG_INF, NEG_INF, NEG_INF);
    }

    // local argmax (first-max semantics: strided layout is index-increasing per lane)
    float bmax = NEG_INF;
    int   bidx = 0x7fffffff;
    #pragma unroll
    for (int k = 0; k < VPT; k++) {
        int base = (lane + 32 * k) * 4;
        if (t[k].x > bmax) { bmax = t[k].x; bidx = base + 0; }
        if (t[k].y > bmax) { bmax = t[k].y; bidx = base + 1; }
        if (t[k].z > bmax) { bmax = t[k].z; bidx = base + 2; }
        if (t[k].w > bmax) { bmax = t[k].w; bidx = base + 3; }
    }

    // warp butterfly argmax ((max, min-index) is assoc+comm)
    #pragma unroll
    for (int o = 16; o > 0; o >>= 1) {
        float ov = __shfl_xor_sync(0xffffffffu, bmax, o);
        int   oi = __shfl_xor_sync(0xffffffffu, bidx, o);
        if (ov > bmax || (ov == bmax && oi < bidx)) { bmax = ov; bidx = oi; }
    }

    if (lane == 0) g_labels[row] = bidx;
}

// ================= K2: hinge sum over logits =================
__global__ __launch_bounds__(NTHREADS, 5)
void hinge_kernel(const float* __restrict__ logits,
                  float* __restrict__ out,
                  int B) {
    const int lane = threadIdx.x & 31;
    const int wid  = threadIdx.x >> 5;
    const int row  = blockIdx.x * ROWS_PER_CTA + wid;

    // issue label load first (L2-resident 4B) so it's back before we need it
    const int label = g_labels[row];

    const float4* lg = reinterpret_cast<const float4*>(logits + (size_t)row * C_DIM);
    const float NEG_INF = -3.402823466e+38f;

    // single batched load phase: 8 float4 per lane
    float4 l[VPT];
    #pragma unroll
    for (int k = 0; k < VPT; k++) {
        int v = lane + 32 * k;
        if (v < C_VEC) l[k] = lg[v];
        else           l[k] = make_float4(NEG_INF, NEG_INF, NEG_INF, NEG_INF); // guarded out below
    }

    // x1 = logits[row][label] extracted from registers via shuffle.
    // label is warp-uniform (same g_labels[row] on all lanes).
    const int lvec  = label >> 2;
    const int owner = lvec & 31;
    const int slot  = lvec >> 5;
    const int comp  = label & 3;
    float x1;
    {
        float4 lv;
        switch (slot) {
            case 0: lv = l[0]; break;
            case 1: lv = l[1]; break;
            case 2: lv = l[2]; break;
            case 3: lv = l[3]; break;
            case 4: lv = l[4]; break;
            case 5: lv = l[5]; break;
            case 6: lv = l[6]; break;
            default: lv = l[7]; break;
        }
        float c = (comp == 0) ? lv.x : (comp == 1) ? lv.y : (comp == 2) ? lv.z : lv.w;
        x1 = __shfl_sync(0xffffffffu, c, owner);
    }

    const float inv  = 1.0f / (float)(C_DIM - 1);
    const float labf = (float)label;

    // hinge sum: margin(0)=1.0 (neg term, NEG_MARGIN=1 folds in exactly),
    // margin(j)=|label-j|/(C-1) for j>=1.
    float acc = 0.0f;
    #pragma unroll
    for (int k = 0; k < VPT; k++) {
        int v = lane + 32 * k;
        if (v < C_VEC) {
            float jf = (float)(v * 4);
            float m0 = (v == 0 && lane == 0) ? 1.0f : fabsf(labf - jf) * inv;
            float m1 = fabsf(labf - (jf + 1.0f)) * inv;
            float m2 = fabsf(labf - (jf + 2.0f)) * inv;
            float m3 = fabsf(labf - (jf + 3.0f)) * inv;
            acc += fmaxf(0.0f, l[k].x - x1 + m0);
            acc += fmaxf(0.0f, l[k].y - x1 + m1);
            acc += fmaxf(0.0f, l[k].z - x1 + m2);
            acc += fmaxf(0.0f, l[k].w - x1 + m3);
        }
    }

    // warp sum reduce
    #pragma unroll
    for (int o = 16; o > 0; o >>= 1)
        acc += __shfl_xor_sync(0xffffffffu, acc, o);

    float row_val = (label != 0) ? acc * (1.0f / (float)B) : 0.0f;

    // CTA partial reduce, single atomic per CTA
    __shared__ float s_sum[ROWS_PER_CTA];
    if (lane == 0) s_sum[wid] = row_val;
    __syncthreads();

    if (threadIdx.x == 0) {
        float cta = 0.0f;
        #pragma unroll
        for (int w = 0; w < ROWS_PER_CTA; w++) cta += s_sum[w];
        atomicAdd(&g_scratch, cta);
        __threadfence();
        unsigned int done = atomicAdd(&g_count, 1u);
        if (done == gridDim.x - 1) {
            float total = *((volatile float*)&g_scratch);
            out[0] = total;
            g_scratch = 0.0f;   // reset for next graph replay
            g_count   = 0u;
            __threadfence();
        }
    }
}

extern "C" void kernel_launch(void* const* d_in, const int* in_sizes, int n_in,
                              void* d_out, int out_size) {
    const float* logits = (const float*)d_in[0];
    const float* target = (const float*)d_in[1];
    float* out = (float*)d_out;
    const int B = in_sizes[0] / C_DIM;       // 16384
    const int grid = B / ROWS_PER_CTA;       // 2048

    argmax_kernel<<<grid, NTHREADS>>>(target);
    hinge_kernel <<<grid, NTHREADS>>>(logits, out, B);
}

// round 9
// speedup vs baseline: 1.0654x; 1.0654x over previous
#include <cuda_runtime.h>
#include <cuda_bf16.h>
#include <cstdint>

#define C_DIM 1000
#define C_VEC 250            // C_DIM / 4
#define VPT 8                // ceil(C_VEC / 32)
#define WARPS_PER_CTA 3
#define NTHREADS (WARPS_PER_CTA * 32)
#define GRID_DIM 592                      // 4 CTAs/SM x 148 SMs, one perfect wave
#define NW_TOTAL (GRID_DIM * WARPS_PER_CTA)  // 1776 warp-streams
#define B_DIM 16384

__device__ float        g_scratch = 0.0f;
__device__ unsigned int g_count   = 0;

__global__ __launch_bounds__(NTHREADS)
void ranking_stream_kernel(const float* __restrict__ logits,
                           const float* __restrict__ target,
                           float* __restrict__ out,
                           int B) {
    // [warp][stage][array(0=target,1=logits)][vec]  -> 3*2*2*256*16B = 49152B (48KB exact)
    __shared__ float4 s_buf[WARPS_PER_CTA][2][2][256];
    __shared__ float  s_warp[WARPS_PER_CTA];

    const int lane = threadIdx.x & 31;
    const int wid  = threadIdx.x >> 5;
    const int gw   = blockIdx.x * WARPS_PER_CTA + wid;   // global warp-stream id

    const float inv   = 1.0f / (float)(C_DIM - 1);
    const float NEG_INF = -3.402823466e+38f;

    // ---- async prefetch of one row (target + logits) into a stage ----
    auto prefetch = [&](int row, int stage) {
        const float4* tg = reinterpret_cast<const float4*>(target + (size_t)row * C_DIM);
        const float4* lg = reinterpret_cast<const float4*>(logits + (size_t)row * C_DIM);
        #pragma unroll
        for (int k = 0; k < VPT; k++) {
            int v = lane + 32 * k;
            if (v < C_VEC) {
                unsigned dt = (unsigned)__cvta_generic_to_shared(&s_buf[wid][stage][0][v]);
                asm volatile("cp.async.cg.shared.global [%0], [%1], 16;\n"
                             :: "r"(dt), "l"(tg + v));
                unsigned dl = (unsigned)__cvta_generic_to_shared(&s_buf[wid][stage][1][v]);
                asm volatile("cp.async.cg.shared.global [%0], [%1], 16;\n"
                             :: "r"(dl), "l"(lg + v));
            }
        }
        asm volatile("cp.async.commit_group;\n");
    };

    float lane_acc = 0.0f;     // per-lane hinge accumulation across all rows
    int   stage    = 0;

    if (gw < B) prefetch(gw, 0);

    for (int row = gw; row < B; row += NW_TOTAL) {
        int next = row + NW_TOTAL;
        if (next < B) {
            prefetch(next, stage ^ 1);
            asm volatile("cp.async.wait_group 1;\n");   // current row's group done
        } else {
            asm volatile("cp.async.wait_group 0;\n");
        }
        __syncwarp();                                    // cross-lane smem visibility

        const float4* ts = (const float4*)s_buf[wid][stage][0];
        const float4* ls = (const float4*)s_buf[wid][stage][1];

        // ---- argmax over target row (first-max; per-lane indices ascending) ----
        float bmax = NEG_INF;
        int   bidx = 0x7fffffff;
        #pragma unroll
        for (int k = 0; k < VPT; k++) {
            int v = lane + 32 * k;
            if (v < C_VEC) {
                float4 t = ts[v];
                int base = v * 4;
                if (t.x > bmax) { bmax = t.x; bidx = base + 0; }
                if (t.y > bmax) { bmax = t.y; bidx = base + 1; }
                if (t.z > bmax) { bmax = t.z; bidx = base + 2; }
                if (t.w > bmax) { bmax = t.w; bidx = base + 3; }
            }
        }
        #pragma unroll
        for (int o = 16; o > 0; o >>= 1) {
            float ov = __shfl_xor_sync(0xffffffffu, bmax, o);
            int   oi = __shfl_xor_sync(0xffffffffu, bidx, o);
            if (ov > bmax || (ov == bmax && oi < bidx)) { bmax = ov; bidx = oi; }
        }
        const int   label = bidx;
        const float labf  = (float)label;

        // x1: uniform-address smem read -> broadcast, conflict-free
        const float x1 = ((const float*)ls)[label];

        // ---- hinge: margin(0)=1.0 (neg term, NEG_MARGIN=1), margin(j)=|label-j|/999 ----
        float acc = 0.0f;
        #pragma unroll
        for (int k = 0; k < VPT; k++) {
            int v = lane + 32 * k;
            if (v < C_VEC) {
                float4 l = ls[v];
                float jf = (float)(v * 4);
                float m0 = (v == 0 && lane == 0) ? 1.0f : fabsf(labf - jf) * inv;
                float m1 = fabsf(labf - (jf + 1.0f)) * inv;
                float m2 = fabsf(labf - (jf + 2.0f)) * inv;
                float m3 = fabsf(labf - (jf + 3.0f)) * inv;
                acc += fmaxf(0.0f, l.x - x1 + m0);
                acc += fmaxf(0.0f, l.y - x1 + m1);
                acc += fmaxf(0.0f, l.z - x1 + m2);
                acc += fmaxf(0.0f, l.w - x1 + m3);
            }
        }
        if (label != 0) lane_acc += acc;   // label warp-uniform: consistent zeroing
        stage ^= 1;
    }

    // ---- one butterfly sum at the very end ----
    #pragma unroll
    for (int o = 16; o > 0; o >>= 1)
        lane_acc += __shfl_xor_sync(0xffffffffu, lane_acc, o);
    if (lane == 0) s_warp[wid] = lane_acc * (1.0f / (float)B);
    __syncthreads();

    if (threadIdx.x == 0) {
        float cta = 0.0f;
        #pragma unroll
        for (int w = 0; w < WARPS_PER_CTA; w++) cta += s_warp[w];
        atomicAdd(&g_scratch, cta);
        __threadfence();
        unsigned int done = atomicAdd(&g_count, 1u);
        if (done == gridDim.x - 1) {
            float total = *((volatile float*)&g_scratch);
            out[0] = total;
            g_scratch = 0.0f;   // reset for next graph replay
            g_count   = 0u;
            __threadfence();
        }
    }
}

extern "C" void kernel_launch(void* const* d_in, const int* in_sizes, int n_in,
                              void* d_out, int out_size) {
    const float* logits = (const float*)d_in[0];
    const float* target = (const float*)d_in[1];
    float* out = (float*)d_out;
    const int B = in_sizes[0] / C_DIM;   // 16384

    ranking_stream_kernel<<<GRID_DIM, NTHREADS>>>(logits, target, out, B);
}